// round 8
// baseline (speedup 1.0000x reference)
#include <cuda_runtime.h>
#include <cuda_fp16.h>
#include <cstdint>

// ----------------------------------------------------------------------------
// Packed bidirectional 2-layer LSTM.
//   inputs : input(total,256) f32, batch_sizes(T) i32, h0(4,64,128), c0(4,64,128),
//            W_ih(4,512,256), W_hh(4,512,128), b_ih(4,512), b_hh(4,512)
//   outputs: packed_out(total,256) | h_n(4,64,128) | c_n(4,64,128)
// ----------------------------------------------------------------------------

#define TOTAL_MAX 49408
#define TMAX      1024
#define AK        72            // padded smem stride in halves (144B, conflict-free)

__device__ float  g_gpre[2 * TOTAL_MAX * 512];
__device__ __half g_A16 [TOTAL_MAX * 256];      // layer-0 input, fp16
__device__ __half g_out1h[TOTAL_MAX * 256];     // layer-1 input (rec-l0 output), fp16
__device__ __half g_W16 [4 * 512 * 256];        // W_ih in fp16
__device__ int    g_offsets[TMAX];
__device__ int    g_len[64];

typedef unsigned long long ull;

__device__ __forceinline__ ull ffma2(ull a, ull b, ull c)
{
    ull d;
    asm("fma.rn.f32x2 %0, %1, %2, %3;" : "=l"(d) : "l"(a), "l"(b), "l"(c));
    return d;
}
__device__ __forceinline__ ull packf2(float lo, float hi)
{
    ull r;
    asm("mov.b64 %0, {%1, %2};" : "=l"(r) : "f"(lo), "f"(hi));
    return r;
}
__device__ __forceinline__ float2 unpackf2(ull v)
{
    float2 f;
    asm("mov.b64 {%0, %1}, %2;" : "=f"(f.x), "=f"(f.y) : "l"(v));
    return f;
}
__device__ __forceinline__ __half2 uh2(unsigned int u)
{
    return *reinterpret_cast<__half2*>(&u);
}
__device__ __forceinline__ unsigned int h2u(__half2 h)
{
    return *reinterpret_cast<unsigned int*>(&h);
}

// ---- HMMA building blocks ----
__device__ __forceinline__ void cp16(uint32_t saddr, const void* gptr)
{
    asm volatile("cp.async.cg.shared.global [%0], [%1], 16;"
                 :: "r"(saddr), "l"(gptr) : "memory");
}
__device__ __forceinline__ void ldsm_x4(uint32_t& r0, uint32_t& r1,
                                        uint32_t& r2, uint32_t& r3, uint32_t addr)
{
    asm volatile("ldmatrix.sync.aligned.m8n8.x4.shared.b16 {%0,%1,%2,%3}, [%4];"
                 : "=r"(r0), "=r"(r1), "=r"(r2), "=r"(r3) : "r"(addr));
}
__device__ __forceinline__ void ldsm_x2(uint32_t& r0, uint32_t& r1, uint32_t addr)
{
    asm volatile("ldmatrix.sync.aligned.m8n8.x2.shared.b16 {%0,%1}, [%2];"
                 : "=r"(r0), "=r"(r1) : "r"(addr));
}
__device__ __forceinline__ void mma16816(float* c,
                                         uint32_t a0, uint32_t a1, uint32_t a2, uint32_t a3,
                                         uint32_t b0, uint32_t b1)
{
    asm volatile("mma.sync.aligned.m16n8k16.row.col.f32.f16.f16.f32 "
                 "{%0,%1,%2,%3}, {%4,%5,%6,%7}, {%8,%9}, {%0,%1,%2,%3};"
                 : "+f"(c[0]), "+f"(c[1]), "+f"(c[2]), "+f"(c[3])
                 : "r"(a0), "r"(a1), "r"(a2), "r"(a3), "r"(b0), "r"(b1));
}

// ---------------------------------------------------------------- setup -----
__global__ void setup_kernel(const int* __restrict__ bs, int T)
{
    __shared__ int s[TMAX];
    int tid = threadIdx.x;
    if (tid < T) s[tid] = bs[tid];
    __syncthreads();
    if (tid == 0) {
        int off = 0;
        for (int t = 0; t < T; ++t) { g_offsets[t] = off; off += s[t]; }
    }
    if (tid < 64) {
        int c = 0;
        for (int t = 0; t < T; ++t) c += (s[t] > tid) ? 1 : 0;
        g_len[tid] = c;
    }
}

// f32 -> f16 bulk convert (float4 granularity)
__global__ void cvt_kernel(const float* __restrict__ src, __half* __restrict__ dst, int n4)
{
    int i = blockIdx.x * blockDim.x + threadIdx.x;
    if (i < n4) {
        float4 v = reinterpret_cast<const float4*>(src)[i];
        __half2 lo = __floats2half2_rn(v.x, v.y);
        __half2 hi = __floats2half2_rn(v.z, v.w);
        uint2 u;
        u.x = h2u(lo);
        u.y = h2u(hi);
        reinterpret_cast<uint2*>(dst)[i] = u;
    }
}

// ------------------------------------------------------------ HMMA gemm -----
// gpre[dir][tok][g] = A16[tok][:] . W16[layer][dir*512+g][:] + bias
// CTA tile 128(m) x 128(n). K=256 in 4 stages of 64, double-buffered cp.async.
// 8 warps: warpM(2) x warpN(4); warp tile 64x32; mma.m16n8k16 f16 -> f32.
__global__ __launch_bounds__(256, 2)
void gemm_hmma(const __half* __restrict__ Ah,
               const float* __restrict__ bih_all,
               const float* __restrict__ bhh_all,
               int total, int layer)
{
    extern __shared__ __half shbuf[];
    const int STAGE = 2 * 128 * AK;                 // halves per stage (A + B tiles)
    const uint32_t sbase = (uint32_t)__cvta_generic_to_shared(shbuf);

    const __half* Wl = g_W16 + (size_t)layer * 262144;
    const float*  bi = bih_all + layer * 1024;
    const float*  bh = bhh_all + layer * 1024;

    const int tid   = threadIdx.x;
    const int lane  = tid & 31;
    const int wid   = tid >> 5;
    const int warpM = wid >> 2;                     // 0..1
    const int warpN = wid & 3;                      // 0..3
    const int mBase = blockIdx.x * 128;
    const int nBase = blockIdx.y * 128;

    const int r0 = tid >> 3;                        // cp.async row (0..31)
    const int c0 = tid & 7;                         // 16B chunk (0..7)

    const int grp  = lane >> 3;
    const int rinl = lane & 7;
    const int aRow = warpM * 64 + (grp & 1) * 8 + rinl;
    const int aCol = (grp >> 1) * 8;
    const int bRowBase = warpN * 32 + rinl;
    const int bCol = ((lane >> 3) & 1) * 8;

    float acc[4][4][4];
#pragma unroll
    for (int i = 0; i < 4; ++i)
#pragma unroll
        for (int j = 0; j < 4; ++j)
#pragma unroll
            for (int v = 0; v < 4; ++v) acc[i][j][v] = 0.f;

    // ---- prologue: stage 0 into buffer 0
#pragma unroll
    for (int i = 0; i < 4; ++i) {
        int r = r0 + i * 32;
        int arow = mBase + r;
        if (arow > total - 1) arow = total - 1;
        cp16(sbase + (uint32_t)(r * AK + c0 * 8) * 2,
             Ah + (size_t)arow * 256 + c0 * 8);
        cp16(sbase + (uint32_t)(128 * AK + r * AK + c0 * 8) * 2,
             Wl + (size_t)(nBase + r) * 256 + c0 * 8);
    }
    asm volatile("cp.async.commit_group;" ::: "memory");

    for (int s = 0; s < 4; ++s) {
        if (s < 3) {
            const int ks  = s + 1;
            const int nbf = ks & 1;
#pragma unroll
            for (int i = 0; i < 4; ++i) {
                int r = r0 + i * 32;
                int arow = mBase + r;
                if (arow > total - 1) arow = total - 1;
                cp16(sbase + (uint32_t)(nbf * STAGE + r * AK + c0 * 8) * 2,
                     Ah + (size_t)arow * 256 + ks * 64 + c0 * 8);
                cp16(sbase + (uint32_t)(nbf * STAGE + 128 * AK + r * AK + c0 * 8) * 2,
                     Wl + (size_t)(nBase + r) * 256 + ks * 64 + c0 * 8);
            }
        }
        asm volatile("cp.async.commit_group;" ::: "memory");
        if (s < 3) asm volatile("cp.async.wait_group 1;" ::: "memory");
        else       asm volatile("cp.async.wait_group 0;" ::: "memory");
        __syncthreads();

        const int buf = s & 1;
        const uint32_t aTile = sbase + (uint32_t)(buf * STAGE) * 2;
        const uint32_t bTile = sbase + (uint32_t)(buf * STAGE + 128 * AK) * 2;

#pragma unroll
        for (int kk = 0; kk < 4; ++kk) {
            uint32_t af[4][4];
            uint32_t bf[4][2];
#pragma unroll
            for (int mf = 0; mf < 4; ++mf) {
                uint32_t aaddr = aTile +
                    (uint32_t)((aRow + mf * 16) * AK + kk * 16 + aCol) * 2;
                ldsm_x4(af[mf][0], af[mf][1], af[mf][2], af[mf][3], aaddr);
            }
#pragma unroll
            for (int nf = 0; nf < 4; ++nf) {
                uint32_t baddr = bTile +
                    (uint32_t)((bRowBase + nf * 8) * AK + kk * 16 + bCol) * 2;
                ldsm_x2(bf[nf][0], bf[nf][1], baddr);
            }
#pragma unroll
            for (int mf = 0; mf < 4; ++mf)
#pragma unroll
                for (int nf = 0; nf < 4; ++nf)
                    mma16816(acc[mf][nf],
                             af[mf][0], af[mf][1], af[mf][2], af[mf][3],
                             bf[nf][0], bf[nf][1]);
        }
        __syncthreads();
    }

    // ---- epilogue: bias add + scatter to g_gpre[dir][tok][g]
    const int mW = mBase + warpM * 64 + (lane >> 2);
    const int nW = nBase + warpN * 32 + ((lane & 3) << 1);
#pragma unroll
    for (int nf = 0; nf < 4; ++nf) {
        int n = nW + nf * 8;
        float bias0 = bi[n] + bh[n];
        float bias1 = bi[n + 1] + bh[n + 1];
        int dirr = n >> 9;
        int g    = n & 511;
        float* gp = g_gpre + (size_t)dirr * (size_t)total * 512 + g;
#pragma unroll
        for (int mf = 0; mf < 4; ++mf) {
            int m0 = mW + mf * 16;
            if (m0 < total) {
                float2 v = make_float2(acc[mf][nf][0] + bias0, acc[mf][nf][1] + bias1);
                *reinterpret_cast<float2*>(gp + (size_t)m0 * 512) = v;
            }
            int m1 = m0 + 8;
            if (m1 < total) {
                float2 v = make_float2(acc[mf][nf][2] + bias0, acc[mf][nf][3] + bias1);
                *reinterpret_cast<float2*>(gp + (size_t)m1 * 512) = v;
            }
        }
    }
}

// ------------------------------------------------------------- recurrence ---
__device__ __forceinline__ float sigf(float x)
{
    return __fdividef(1.0f, 1.0f + __expf(-x));
}
__device__ __forceinline__ float tanhfast(float x)
{
    x = fminf(fmaxf(x, -12.0f), 12.0f);
    float e = __expf(2.0f * x);
    return __fdividef(e - 1.0f, e + 1.0f);
}

// 128 CTAs: blockIdx.x = dir*64 + b. 256 threads (8 warps).
// Gate layout: warp w, lane L -> cell = w*16 + (L&15); L<16 computes (i,f),
// L>=16 computes (g,o). Cell's 4 gates live in one warp -> combine via two
// shfl.xor(16); NO z SMEM exchange, ONE barrier/step, ping-pong h buffers.
// W_hh register-resident: k<64 fp32 f32x2 pairs, k>=64 fp16 half2 (HFMA2).
__global__ __launch_bounds__(256, 1)
void rec_kernel(const float* __restrict__ Whh_all,
                const float* __restrict__ h0,
                const float* __restrict__ c0,
                float* __restrict__ dout,
                int total, int T, int layer)
{
    __shared__ __align__(16) float  hs[2][128];
    __shared__ __align__(16) __half hsh[2][64];
    __shared__ int offs[TMAX];

    const int tid  = threadIdx.x;
    const int lane = tid & 31;
    const int w    = tid >> 5;
    const int hlf  = lane >> 4;                 // 0: (i,f)  1: (g,o)
    const int cell = w * 16 + (lane & 15);
    const int row0 = hlf * 256 + cell;          // i (0..127) or g (256..383)
    const int row1 = row0 + 128;                // f or o
    const int dir  = blockIdx.x >> 6;
    const int b    = blockIdx.x & 63;
    const int kix  = 2 * layer + dir;

    const float* gpd = g_gpre + (size_t)dir * (size_t)total * 512;
    const float* W   = Whh_all + (size_t)kix * 512 * 128;

    for (int i = tid; i < T; i += 256) offs[i] = g_offsets[i];

    // k < 64 -> fp32 f32x2 register pairs (2 rows x 32 pairs)
    ull wr[2][32];
    // k >= 64 -> fp16 half2 registers (2 rows x 32 half2)
    unsigned int whr[2][32];
#pragma unroll
    for (int e = 0; e < 2; ++e) {
        const int row = (e == 0) ? row0 : row1;
        const float* wg = &W[row * 128];
#pragma unroll
        for (int p = 0; p < 32; ++p) {
            float2 wv = *reinterpret_cast<const float2*>(&wg[2 * p]);
            wr[e][p] = packf2(wv.x, wv.y);
        }
#pragma unroll
        for (int c = 0; c < 8; ++c) {
            float4 w0 = *reinterpret_cast<const float4*>(&wg[64 + c * 8]);
            float4 w1 = *reinterpret_cast<const float4*>(&wg[64 + c * 8 + 4]);
            whr[e][c * 4 + 0] = h2u(__floats2half2_rn(w0.x, w0.y));
            whr[e][c * 4 + 1] = h2u(__floats2half2_rn(w0.z, w0.w));
            whr[e][c * 4 + 2] = h2u(__floats2half2_rn(w1.x, w1.y));
            whr[e][c * 4 + 3] = h2u(__floats2half2_rn(w1.z, w1.w));
        }
    }

    float creg = 0.f;
    if (lane < 16) {
        float hv = h0[(size_t)kix * 8192 + b * 128 + cell];
        hs[0][cell] = hv;
        if (cell >= 64) hsh[0][cell - 64] = __float2half_rn(hv);
        creg = c0[(size_t)kix * 8192 + b * 128 + cell];
    }
    __syncthreads();

    const int  len = g_len[b];
    const bool fwd = (dir == 0);

    int   tok = offs[fwd ? 0 : (len - 1)] + b;
    float gcur0 = gpd[(size_t)tok * 512 + row0];
    float gcur1 = gpd[(size_t)tok * 512 + row1];

    const __half2 hzero = __floats2half2_rn(0.f, 0.f);
    int p = 0;

    for (int s = 0; s < len; ++s) {
        // prefetch next step's gate preactivations (hide dependent LDG latency)
        int   toknext = 0;
        float gnext0 = 0.f, gnext1 = 0.f;
        if (s + 1 < len) {
            int tn  = fwd ? (s + 1) : (len - 2 - s);
            toknext = offs[tn] + b;
            gnext0  = gpd[(size_t)toknext * 512 + row0];
            gnext1  = gpd[(size_t)toknext * 512 + row1];
        }

        const double2* h2p = reinterpret_cast<const double2*>(hs[p]);
        const uint4*   hhp = reinterpret_cast<const uint4*>(hsh[p]);

        float z0, z1;
#pragma unroll
        for (int e = 0; e < 2; ++e) {
            ull a0 = 0ull, a1 = 0ull;
#pragma unroll
            for (int q = 0; q < 16; ++q) {
                double2 h2 = h2p[q];
                a0 = ffma2(wr[e][2 * q],     __double_as_longlong(h2.x), a0);
                a1 = ffma2(wr[e][2 * q + 1], __double_as_longlong(h2.y), a1);
            }
            __half2 hc0 = hzero, hc1 = hzero;
#pragma unroll
            for (int c = 0; c < 8; ++c) {
                uint4 hv = hhp[c];
                hc0 = __hfma2(uh2(whr[e][c * 4 + 0]), uh2(hv.x), hc0);
                hc1 = __hfma2(uh2(whr[e][c * 4 + 1]), uh2(hv.y), hc1);
                hc0 = __hfma2(uh2(whr[e][c * 4 + 2]), uh2(hv.z), hc0);
                hc1 = __hfma2(uh2(whr[e][c * 4 + 3]), uh2(hv.w), hc1);
            }
            float2 fa = unpackf2(a0);
            float2 fb = unpackf2(a1);
            float2 f0 = __half22float2(hc0);
            float2 f1 = __half22float2(hc1);
            float zz = ((e == 0) ? gcur0 : gcur1)
                     + (fa.x + fa.y) + (fb.x + fb.y)
                     + (f0.x + f0.y) + (f1.x + f1.y);
            if (e == 0) z0 = zz; else z1 = zz;
        }

        // exchange the partner gate pair within the warp
        float zp0 = __shfl_xor_sync(0xffffffffu, z0, 16);
        float zp1 = __shfl_xor_sync(0xffffffffu, z1, 16);

        if (lane < 16) {
            // own: (zi, zf)  partner: (zg, zo)
            float ig = sigf(z0);
            float fg = sigf(z1);
            float gv = tanhfast(zp0);
            float og = sigf(zp1);
            creg = fg * creg + ig * gv;
            float hv = og * tanhfast(creg);
            hs[p ^ 1][cell] = hv;
            if (cell >= 64) hsh[p ^ 1][cell - 64] = __float2half_rn(hv);
            if (layer == 0)
                g_out1h[(size_t)tok * 256 + dir * 128 + cell] = __float2half_rn(hv);
            else
                dout[(size_t)tok * 256 + dir * 128 + cell] = hv;
        }
        __syncthreads();
        p ^= 1;

        gcur0 = gnext0;
        gcur1 = gnext1;
        tok   = toknext;
    }

    if (lane < 16) {
        float* hn = dout + (size_t)total * 256 + (size_t)kix * 8192 + (size_t)b * 128;
        float* cn = hn + 4 * 64 * 128;
        hn[cell] = hs[p][cell];
        cn[cell] = creg;
    }
}

// ---------------------------------------------------------------- launch ----
extern "C" void kernel_launch(void* const* d_in, const int* in_sizes, int n_in,
                              void* d_out, int out_size)
{
    const float* input       = (const float*)d_in[0];
    const int*   batch_sizes = (const int*)  d_in[1];
    const float* h0          = (const float*)d_in[2];
    const float* c0          = (const float*)d_in[3];
    const float* W_ih        = (const float*)d_in[4];
    const float* W_hh        = (const float*)d_in[5];
    const float* b_ih        = (const float*)d_in[6];
    const float* b_hh        = (const float*)d_in[7];
    float* out = (float*)d_out;

    int T     = in_sizes[1];
    int total = in_sizes[0] / 256;
    if (total > TOTAL_MAX) total = TOTAL_MAX;
    if (T > TMAX) T = TMAX;

    const int GEMM_SMEM = 2 * (2 * 128 * AK) * 2;                // 73728 B
    cudaFuncSetAttribute(gemm_hmma, cudaFuncAttributeMaxDynamicSharedMemorySize, GEMM_SMEM);

    setup_kernel<<<1, 1024>>>(batch_sizes, T);

    // fp16 prepass: layer-0 A and all W_ih
    __half* dA16;   cudaGetSymbolAddress((void**)&dA16, g_A16);
    __half* dW16;   cudaGetSymbolAddress((void**)&dW16, g_W16);
    __half* dOut1h; cudaGetSymbolAddress((void**)&dOut1h, g_out1h);
    {
        int n4a = in_sizes[0] / 4;
        int n4w = in_sizes[4] / 4;
        cvt_kernel<<<(n4a + 255) / 256, 256>>>(input, dA16, n4a);
        cvt_kernel<<<(n4w + 255) / 256, 256>>>(W_ih, dW16, n4w);
    }

    dim3 ggrid((total + 127) / 128, 8);
    // layer 0
    gemm_hmma<<<ggrid, 256, GEMM_SMEM>>>(dA16, b_ih, b_hh, total, 0);
    rec_kernel<<<128, 256>>>(W_hh, h0, c0, out, total, T, 0);
    // layer 1
    gemm_hmma<<<ggrid, 256, GEMM_SMEM>>>(dOut1h, b_ih, b_hh, total, 1);
    rec_kernel<<<128, 256>>>(W_hh, h0, c0, out, total, T, 1);
}

// round 9
// speedup vs baseline: 1.3105x; 1.3105x over previous
#include <cuda_runtime.h>
#include <cuda_fp16.h>
#include <cstdint>

// ----------------------------------------------------------------------------
// Packed bidirectional 2-layer LSTM.
//   inputs : input(total,256) f32, batch_sizes(T) i32, h0(4,64,128), c0(4,64,128),
//            W_ih(4,512,256), W_hh(4,512,128), b_ih(4,512), b_hh(4,512)
//   outputs: packed_out(total,256) | h_n(4,64,128) | c_n(4,64,128)
// ----------------------------------------------------------------------------

#define TOTAL_MAX 49408
#define TMAX      1024
#define AK        72            // padded smem stride in halves (144B, conflict-free)

__device__ float  g_gpre[2 * TOTAL_MAX * 512];
__device__ __half g_A16 [TOTAL_MAX * 256];      // layer-0 input, fp16
__device__ __half g_out1h[TOTAL_MAX * 256];     // layer-1 input (rec-l0 output), fp16
__device__ __half g_W16 [4 * 512 * 256];        // W_ih in fp16
__device__ int    g_offsets[TMAX];
__device__ int    g_len[64];

typedef unsigned long long ull;

__device__ __forceinline__ ull ffma2(ull a, ull b, ull c)
{
    ull d;
    asm("fma.rn.f32x2 %0, %1, %2, %3;" : "=l"(d) : "l"(a), "l"(b), "l"(c));
    return d;
}
__device__ __forceinline__ ull packf2(float lo, float hi)
{
    ull r;
    asm("mov.b64 %0, {%1, %2};" : "=l"(r) : "f"(lo), "f"(hi));
    return r;
}
__device__ __forceinline__ float2 unpackf2(ull v)
{
    float2 f;
    asm("mov.b64 {%0, %1}, %2;" : "=f"(f.x), "=f"(f.y) : "l"(v));
    return f;
}
__device__ __forceinline__ __half2 uh2(unsigned int u)
{
    return *reinterpret_cast<__half2*>(&u);
}
__device__ __forceinline__ unsigned int h2u(__half2 h)
{
    return *reinterpret_cast<unsigned int*>(&h);
}

// ---- HMMA building blocks ----
__device__ __forceinline__ void cp16(uint32_t saddr, const void* gptr)
{
    asm volatile("cp.async.cg.shared.global [%0], [%1], 16;"
                 :: "r"(saddr), "l"(gptr) : "memory");
}
__device__ __forceinline__ void ldsm_x4(uint32_t& r0, uint32_t& r1,
                                        uint32_t& r2, uint32_t& r3, uint32_t addr)
{
    asm volatile("ldmatrix.sync.aligned.m8n8.x4.shared.b16 {%0,%1,%2,%3}, [%4];"
                 : "=r"(r0), "=r"(r1), "=r"(r2), "=r"(r3) : "r"(addr));
}
__device__ __forceinline__ void ldsm_x2(uint32_t& r0, uint32_t& r1, uint32_t addr)
{
    asm volatile("ldmatrix.sync.aligned.m8n8.x2.shared.b16 {%0,%1}, [%2];"
                 : "=r"(r0), "=r"(r1) : "r"(addr));
}
__device__ __forceinline__ void mma16816(float* c,
                                         uint32_t a0, uint32_t a1, uint32_t a2, uint32_t a3,
                                         uint32_t b0, uint32_t b1)
{
    asm volatile("mma.sync.aligned.m16n8k16.row.col.f32.f16.f16.f32 "
                 "{%0,%1,%2,%3}, {%4,%5,%6,%7}, {%8,%9}, {%0,%1,%2,%3};"
                 : "+f"(c[0]), "+f"(c[1]), "+f"(c[2]), "+f"(c[3])
                 : "r"(a0), "r"(a1), "r"(a2), "r"(a3), "r"(b0), "r"(b1));
}

// ---------------------------------------------------------------- setup -----
__global__ void setup_kernel(const int* __restrict__ bs, int T)
{
    __shared__ int s[TMAX];
    int tid = threadIdx.x;
    if (tid < T) s[tid] = bs[tid];
    __syncthreads();
    if (tid == 0) {
        int off = 0;
        for (int t = 0; t < T; ++t) { g_offsets[t] = off; off += s[t]; }
    }
    if (tid < 64) {
        int c = 0;
        for (int t = 0; t < T; ++t) c += (s[t] > tid) ? 1 : 0;
        g_len[tid] = c;
    }
}

// f32 -> f16 bulk convert (float4 granularity)
__global__ void cvt_kernel(const float* __restrict__ src, __half* __restrict__ dst, int n4)
{
    int i = blockIdx.x * blockDim.x + threadIdx.x;
    if (i < n4) {
        float4 v = reinterpret_cast<const float4*>(src)[i];
        __half2 lo = __floats2half2_rn(v.x, v.y);
        __half2 hi = __floats2half2_rn(v.z, v.w);
        uint2 u;
        u.x = h2u(lo);
        u.y = h2u(hi);
        reinterpret_cast<uint2*>(dst)[i] = u;
    }
}

// ------------------------------------------------------------ HMMA gemm -----
// gpre[dir][tok][g] = A16[tok][:] . W16[layer][dir*512+g][:] + bias
// CTA tile 128(m) x 128(n). K=256 in 4 stages of 64, double-buffered cp.async.
// 8 warps: warpM(2) x warpN(4); warp tile 64x32; mma.m16n8k16 f16 -> f32.
__global__ __launch_bounds__(256, 2)
void gemm_hmma(const __half* __restrict__ Ah,
               const float* __restrict__ bih_all,
               const float* __restrict__ bhh_all,
               int total, int layer)
{
    extern __shared__ __half shbuf[];
    const int STAGE = 2 * 128 * AK;                 // halves per stage (A + B tiles)
    const uint32_t sbase = (uint32_t)__cvta_generic_to_shared(shbuf);

    const __half* Wl = g_W16 + (size_t)layer * 262144;
    const float*  bi = bih_all + layer * 1024;
    const float*  bh = bhh_all + layer * 1024;

    const int tid   = threadIdx.x;
    const int lane  = tid & 31;
    const int wid   = tid >> 5;
    const int warpM = wid >> 2;                     // 0..1
    const int warpN = wid & 3;                      // 0..3
    const int mBase = blockIdx.x * 128;
    const int nBase = blockIdx.y * 128;

    const int r0 = tid >> 3;                        // cp.async row (0..31)
    const int c0 = tid & 7;                         // 16B chunk (0..7)

    const int grp  = lane >> 3;
    const int rinl = lane & 7;
    const int aRow = warpM * 64 + (grp & 1) * 8 + rinl;
    const int aCol = (grp >> 1) * 8;
    const int bRowBase = warpN * 32 + rinl;
    const int bCol = ((lane >> 3) & 1) * 8;

    float acc[4][4][4];
#pragma unroll
    for (int i = 0; i < 4; ++i)
#pragma unroll
        for (int j = 0; j < 4; ++j)
#pragma unroll
            for (int v = 0; v < 4; ++v) acc[i][j][v] = 0.f;

    // ---- prologue: stage 0 into buffer 0
#pragma unroll
    for (int i = 0; i < 4; ++i) {
        int r = r0 + i * 32;
        int arow = mBase + r;
        if (arow > total - 1) arow = total - 1;
        cp16(sbase + (uint32_t)(r * AK + c0 * 8) * 2,
             Ah + (size_t)arow * 256 + c0 * 8);
        cp16(sbase + (uint32_t)(128 * AK + r * AK + c0 * 8) * 2,
             Wl + (size_t)(nBase + r) * 256 + c0 * 8);
    }
    asm volatile("cp.async.commit_group;" ::: "memory");

    for (int s = 0; s < 4; ++s) {
        if (s < 3) {
            const int ks  = s + 1;
            const int nbf = ks & 1;
#pragma unroll
            for (int i = 0; i < 4; ++i) {
                int r = r0 + i * 32;
                int arow = mBase + r;
                if (arow > total - 1) arow = total - 1;
                cp16(sbase + (uint32_t)(nbf * STAGE + r * AK + c0 * 8) * 2,
                     Ah + (size_t)arow * 256 + ks * 64 + c0 * 8);
                cp16(sbase + (uint32_t)(nbf * STAGE + 128 * AK + r * AK + c0 * 8) * 2,
                     Wl + (size_t)(nBase + r) * 256 + ks * 64 + c0 * 8);
            }
        }
        asm volatile("cp.async.commit_group;" ::: "memory");
        if (s < 3) asm volatile("cp.async.wait_group 1;" ::: "memory");
        else       asm volatile("cp.async.wait_group 0;" ::: "memory");
        __syncthreads();

        const int buf = s & 1;
        const uint32_t aTile = sbase + (uint32_t)(buf * STAGE) * 2;
        const uint32_t bTile = sbase + (uint32_t)(buf * STAGE + 128 * AK) * 2;

#pragma unroll
        for (int kk = 0; kk < 4; ++kk) {
            uint32_t af[4][4];
            uint32_t bf[4][2];
#pragma unroll
            for (int mf = 0; mf < 4; ++mf) {
                uint32_t aaddr = aTile +
                    (uint32_t)((aRow + mf * 16) * AK + kk * 16 + aCol) * 2;
                ldsm_x4(af[mf][0], af[mf][1], af[mf][2], af[mf][3], aaddr);
            }
#pragma unroll
            for (int nf = 0; nf < 4; ++nf) {
                uint32_t baddr = bTile +
                    (uint32_t)((bRowBase + nf * 8) * AK + kk * 16 + bCol) * 2;
                ldsm_x2(bf[nf][0], bf[nf][1], baddr);
            }
#pragma unroll
            for (int mf = 0; mf < 4; ++mf)
#pragma unroll
                for (int nf = 0; nf < 4; ++nf)
                    mma16816(acc[mf][nf],
                             af[mf][0], af[mf][1], af[mf][2], af[mf][3],
                             bf[nf][0], bf[nf][1]);
        }
        __syncthreads();
    }

    // ---- epilogue: bias add + scatter to g_gpre[dir][tok][g]
    const int mW = mBase + warpM * 64 + (lane >> 2);
    const int nW = nBase + warpN * 32 + ((lane & 3) << 1);
#pragma unroll
    for (int nf = 0; nf < 4; ++nf) {
        int n = nW + nf * 8;
        float bias0 = bi[n] + bh[n];
        float bias1 = bi[n + 1] + bh[n + 1];
        int dirr = n >> 9;
        int g    = n & 511;
        float* gp = g_gpre + (size_t)dirr * (size_t)total * 512 + g;
#pragma unroll
        for (int mf = 0; mf < 4; ++mf) {
            int m0 = mW + mf * 16;
            if (m0 < total) {
                float2 v = make_float2(acc[mf][nf][0] + bias0, acc[mf][nf][1] + bias1);
                *reinterpret_cast<float2*>(gp + (size_t)m0 * 512) = v;
            }
            int m1 = m0 + 8;
            if (m1 < total) {
                float2 v = make_float2(acc[mf][nf][2] + bias0, acc[mf][nf][3] + bias1);
                *reinterpret_cast<float2*>(gp + (size_t)m1 * 512) = v;
            }
        }
    }
}

// ------------------------------------------------------------- recurrence ---
// HW tanh: single MUFU op (sm_75+), replaces exp+div chains.
__device__ __forceinline__ float tanha(float x)
{
    float y;
    asm("tanh.approx.f32 %0, %1;" : "=f"(y) : "f"(x));
    return y;
}
__device__ __forceinline__ float sigf(float x)
{
    return fmaf(tanha(0.5f * x), 0.5f, 0.5f);
}

// 128 CTAs: blockIdx.x = dir*64 + b. 256 threads, 2 gates/thread (tid, tid+256).
// W_hh fully register-resident: k<64 fp32 f32x2 pairs, k>=64 fp16 half2.
// SMEM only holds h (fp32 + fp16 mirrors), z exchange, and offsets.
__global__ __launch_bounds__(256, 1)
void rec_kernel(const float* __restrict__ Whh_all,
                const float* __restrict__ h0,
                const float* __restrict__ c0,
                float* __restrict__ dout,
                int total, int T, int layer)
{
    __shared__ __align__(16) float  hs[128];
    __shared__ __align__(16) __half hsh[64];
    __shared__ float zs[512];
    __shared__ int   offs[TMAX];

    const int tid = threadIdx.x;
    const int dir = blockIdx.x >> 6;
    const int b   = blockIdx.x & 63;
    const int kix = 2 * layer + dir;

    const float* gpd = g_gpre + (size_t)dir * (size_t)total * 512;
    const float* W   = Whh_all + (size_t)kix * 512 * 128;

    for (int i = tid; i < T; i += 256) offs[i] = g_offsets[i];

    // k < 64 -> fp32 f32x2 register pairs (2 gates x 32 pairs)
    ull wr[2][32];
#pragma unroll
    for (int e = 0; e < 2; ++e) {
        const float* wg = &W[(tid + 256 * e) * 128];
#pragma unroll
        for (int p = 0; p < 32; ++p) {
            float2 wv = *reinterpret_cast<const float2*>(&wg[2 * p]);
            wr[e][p] = packf2(wv.x, wv.y);
        }
    }
    // k >= 64 -> fp16 half2 registers (2 gates x 32 half2)
    unsigned int whr[2][32];
#pragma unroll
    for (int e = 0; e < 2; ++e) {
        const float* wg = &W[(tid + 256 * e) * 128 + 64];
#pragma unroll
        for (int c = 0; c < 8; ++c) {
            float4 w0 = *reinterpret_cast<const float4*>(&wg[c * 8]);
            float4 w1 = *reinterpret_cast<const float4*>(&wg[c * 8 + 4]);
            whr[e][c * 4 + 0] = h2u(__floats2half2_rn(w0.x, w0.y));
            whr[e][c * 4 + 1] = h2u(__floats2half2_rn(w0.z, w0.w));
            whr[e][c * 4 + 2] = h2u(__floats2half2_rn(w1.x, w1.y));
            whr[e][c * 4 + 3] = h2u(__floats2half2_rn(w1.z, w1.w));
        }
    }

    float creg = 0.f;
    if (tid < 128) {
        float hv = h0[(size_t)kix * 8192 + b * 128 + tid];
        hs[tid] = hv;
        if (tid >= 64) hsh[tid - 64] = __float2half_rn(hv);
        creg = c0[(size_t)kix * 8192 + b * 128 + tid];
    }
    __syncthreads();

    const int  len = g_len[b];
    const bool fwd = (dir == 0);

    int   tok = offs[fwd ? 0 : (len - 1)] + b;
    float gcur0 = gpd[(size_t)tok * 512 + tid];
    float gcur1 = gpd[(size_t)tok * 512 + tid + 256];

    const double2* h2p = reinterpret_cast<const double2*>(hs);
    const uint4*   hhp = reinterpret_cast<const uint4*>(hsh);
    const __half2  hzero = __floats2half2_rn(0.f, 0.f);

    for (int s = 0; s < len; ++s) {
        int   toknext = 0;
        float gnext0 = 0.f, gnext1 = 0.f;
        if (s + 1 < len) {
            int tn  = fwd ? (s + 1) : (len - 2 - s);
            toknext = offs[tn] + b;
            gnext0  = gpd[(size_t)toknext * 512 + tid];
            gnext1  = gpd[(size_t)toknext * 512 + tid + 256];
        }

        float z[2];
#pragma unroll
        for (int e = 0; e < 2; ++e) {
            ull a0 = 0ull, a1 = 0ull;
#pragma unroll
            for (int q = 0; q < 16; ++q) {
                double2 h2 = h2p[q];
                a0 = ffma2(wr[e][2 * q],     __double_as_longlong(h2.x), a0);
                a1 = ffma2(wr[e][2 * q + 1], __double_as_longlong(h2.y), a1);
            }
            __half2 hc0 = hzero, hc1 = hzero;
#pragma unroll
            for (int c = 0; c < 8; ++c) {
                uint4 hv = hhp[c];
                hc0 = __hfma2(uh2(whr[e][c * 4 + 0]), uh2(hv.x), hc0);
                hc1 = __hfma2(uh2(whr[e][c * 4 + 1]), uh2(hv.y), hc1);
                hc0 = __hfma2(uh2(whr[e][c * 4 + 2]), uh2(hv.z), hc0);
                hc1 = __hfma2(uh2(whr[e][c * 4 + 3]), uh2(hv.w), hc1);
            }
            float2 fa = unpackf2(a0);
            float2 fb = unpackf2(a1);
            float2 f0 = __half22float2(hc0);
            float2 f1 = __half22float2(hc1);
            z[e] = ((e == 0) ? gcur0 : gcur1)
                 + (fa.x + fa.y) + (fb.x + fb.y)
                 + (f0.x + f0.y) + (f1.x + f1.y);
        }
        zs[tid]       = z[0];
        zs[tid + 256] = z[1];
        __syncthreads();

        if (tid < 128) {
            float zi = zs[tid];
            float zf = zs[tid + 128];
            float zg = zs[tid + 256];
            float zo = zs[tid + 384];
            float ig = sigf(zi);
            float fg = sigf(zf);
            float gv = tanha(zg);
            float og = sigf(zo);
            creg = fg * creg + ig * gv;
            float hv = og * tanha(creg);
            hs[tid] = hv;
            if (tid >= 64) hsh[tid - 64] = __float2half_rn(hv);
            if (layer == 0)
                g_out1h[(size_t)tok * 256 + dir * 128 + tid] = __float2half_rn(hv);
            else
                dout[(size_t)tok * 256 + dir * 128 + tid] = hv;
        }
        __syncthreads();

        gcur0 = gnext0;
        gcur1 = gnext1;
        tok   = toknext;
    }

    if (tid < 128) {
        float* hn = dout + (size_t)total * 256 + (size_t)kix * 8192 + (size_t)b * 128;
        float* cn = hn + 4 * 64 * 128;
        hn[tid] = hs[tid];
        cn[tid] = creg;
    }
}

// ---------------------------------------------------------------- launch ----
extern "C" void kernel_launch(void* const* d_in, const int* in_sizes, int n_in,
                              void* d_out, int out_size)
{
    const float* input       = (const float*)d_in[0];
    const int*   batch_sizes = (const int*)  d_in[1];
    const float* h0          = (const float*)d_in[2];
    const float* c0          = (const float*)d_in[3];
    const float* W_ih        = (const float*)d_in[4];
    const float* W_hh        = (const float*)d_in[5];
    const float* b_ih        = (const float*)d_in[6];
    const float* b_hh        = (const float*)d_in[7];
    float* out = (float*)d_out;

    int T     = in_sizes[1];
    int total = in_sizes[0] / 256;
    if (total > TOTAL_MAX) total = TOTAL_MAX;
    if (T > TMAX) T = TMAX;

    const int GEMM_SMEM = 2 * (2 * 128 * AK) * 2;                // 73728 B
    cudaFuncSetAttribute(gemm_hmma, cudaFuncAttributeMaxDynamicSharedMemorySize, GEMM_SMEM);

    setup_kernel<<<1, 1024>>>(batch_sizes, T);

    // fp16 prepass: layer-0 A and all W_ih
    __half* dA16;   cudaGetSymbolAddress((void**)&dA16, g_A16);
    __half* dW16;   cudaGetSymbolAddress((void**)&dW16, g_W16);
    __half* dOut1h; cudaGetSymbolAddress((void**)&dOut1h, g_out1h);
    {
        int n4a = in_sizes[0] / 4;
        int n4w = in_sizes[4] / 4;
        cvt_kernel<<<(n4a + 255) / 256, 256>>>(input, dA16, n4a);
        cvt_kernel<<<(n4w + 255) / 256, 256>>>(W_ih, dW16, n4w);
    }

    dim3 ggrid((total + 127) / 128, 8);
    // layer 0
    gemm_hmma<<<ggrid, 256, GEMM_SMEM>>>(dA16, b_ih, b_hh, total, 0);
    rec_kernel<<<128, 256>>>(W_hh, h0, c0, out, total, T, 0);
    // layer 1
    gemm_hmma<<<ggrid, 256, GEMM_SMEM>>>(dOut1h, b_ih, b_hh, total, 1);
    rec_kernel<<<128, 256>>>(W_hh, h0, c0, out, total, T, 1);
}

// round 10
// speedup vs baseline: 1.3175x; 1.0053x over previous
#include <cuda_runtime.h>
#include <cuda_fp16.h>
#include <cstdint>

// ----------------------------------------------------------------------------
// Packed bidirectional 2-layer LSTM.
//   inputs : input(total,256) f32, batch_sizes(T) i32, h0(4,64,128), c0(4,64,128),
//            W_ih(4,512,256), W_hh(4,512,128), b_ih(4,512), b_hh(4,512)
//   outputs: packed_out(total,256) | h_n(4,64,128) | c_n(4,64,128)
// ----------------------------------------------------------------------------

#define TOTAL_MAX 49408
#define TMAX      1024
#define AK        72            // padded smem stride in halves (144B, conflict-free)

__device__ float  g_gpre[2 * TOTAL_MAX * 512];
__device__ __half g_A16 [TOTAL_MAX * 256];      // layer-0 input, fp16
__device__ __half g_out1h[TOTAL_MAX * 256];     // layer-1 input (rec-l0 output), fp16
__device__ __half g_W16 [4 * 512 * 256];        // W_ih in fp16
__device__ int    g_offsets[TMAX];
__device__ int    g_len[64];

typedef unsigned long long ull;

__device__ __forceinline__ ull ffma2(ull a, ull b, ull c)
{
    ull d;
    asm("fma.rn.f32x2 %0, %1, %2, %3;" : "=l"(d) : "l"(a), "l"(b), "l"(c));
    return d;
}
__device__ __forceinline__ ull packf2(float lo, float hi)
{
    ull r;
    asm("mov.b64 %0, {%1, %2};" : "=l"(r) : "f"(lo), "f"(hi));
    return r;
}
__device__ __forceinline__ float2 unpackf2(ull v)
{
    float2 f;
    asm("mov.b64 {%0, %1}, %2;" : "=f"(f.x), "=f"(f.y) : "l"(v));
    return f;
}
__device__ __forceinline__ __half2 uh2(unsigned int u)
{
    return *reinterpret_cast<__half2*>(&u);
}
__device__ __forceinline__ unsigned int h2u(__half2 h)
{
    return *reinterpret_cast<unsigned int*>(&h);
}

// ---- HMMA building blocks ----
__device__ __forceinline__ void cp16(uint32_t saddr, const void* gptr)
{
    asm volatile("cp.async.cg.shared.global [%0], [%1], 16;"
                 :: "r"(saddr), "l"(gptr) : "memory");
}
__device__ __forceinline__ void ldsm_x4(uint32_t& r0, uint32_t& r1,
                                        uint32_t& r2, uint32_t& r3, uint32_t addr)
{
    asm volatile("ldmatrix.sync.aligned.m8n8.x4.shared.b16 {%0,%1,%2,%3}, [%4];"
                 : "=r"(r0), "=r"(r1), "=r"(r2), "=r"(r3) : "r"(addr));
}
__device__ __forceinline__ void ldsm_x2(uint32_t& r0, uint32_t& r1, uint32_t addr)
{
    asm volatile("ldmatrix.sync.aligned.m8n8.x2.shared.b16 {%0,%1}, [%2];"
                 : "=r"(r0), "=r"(r1) : "r"(addr));
}
__device__ __forceinline__ void mma16816(float* c,
                                         uint32_t a0, uint32_t a1, uint32_t a2, uint32_t a3,
                                         uint32_t b0, uint32_t b1)
{
    asm volatile("mma.sync.aligned.m16n8k16.row.col.f32.f16.f16.f32 "
                 "{%0,%1,%2,%3}, {%4,%5,%6,%7}, {%8,%9}, {%0,%1,%2,%3};"
                 : "+f"(c[0]), "+f"(c[1]), "+f"(c[2]), "+f"(c[3])
                 : "r"(a0), "r"(a1), "r"(a2), "r"(a3), "r"(b0), "r"(b1));
}

// ---------------------------------------------------------------- setup -----
__global__ void setup_kernel(const int* __restrict__ bs, int T)
{
    __shared__ int s[TMAX];
    int tid = threadIdx.x;
    if (tid < T) s[tid] = bs[tid];
    __syncthreads();
    if (tid == 0) {
        int off = 0;
        for (int t = 0; t < T; ++t) { g_offsets[t] = off; off += s[t]; }
    }
    if (tid < 64) {
        int c = 0;
        for (int t = 0; t < T; ++t) c += (s[t] > tid) ? 1 : 0;
        g_len[tid] = c;
    }
}

// f32 -> f16 bulk convert, both arrays in ONE launch (keeps launch count at 6
// so ncu -s 5 -c 1 captures the layer-1 rec_kernel).
__global__ void cvt_kernel(const float* __restrict__ srcA, __half* __restrict__ dstA, int n4a,
                           const float* __restrict__ srcW, __half* __restrict__ dstW, int n4w)
{
    int i = blockIdx.x * blockDim.x + threadIdx.x;
    const float* src;
    __half* dst;
    int j;
    if (i < n4a) { src = srcA; dst = dstA; j = i; }
    else if (i < n4a + n4w) { src = srcW; dst = dstW; j = i - n4a; }
    else return;
    float4 v = reinterpret_cast<const float4*>(src)[j];
    __half2 lo = __floats2half2_rn(v.x, v.y);
    __half2 hi = __floats2half2_rn(v.z, v.w);
    uint2 u;
    u.x = h2u(lo);
    u.y = h2u(hi);
    reinterpret_cast<uint2*>(dst)[j] = u;
}

// ------------------------------------------------------------ HMMA gemm -----
// gpre[dir][tok][g] = A16[tok][:] . W16[layer][dir*512+g][:] + bias
// CTA tile 128(m) x 128(n). K=256 in 4 stages of 64, double-buffered cp.async.
// 8 warps: warpM(2) x warpN(4); warp tile 64x32; mma.m16n8k16 f16 -> f32.
__global__ __launch_bounds__(256, 2)
void gemm_hmma(const __half* __restrict__ Ah,
               const float* __restrict__ bih_all,
               const float* __restrict__ bhh_all,
               int total, int layer)
{
    extern __shared__ __half shbuf[];
    const int STAGE = 2 * 128 * AK;                 // halves per stage (A + B tiles)
    const uint32_t sbase = (uint32_t)__cvta_generic_to_shared(shbuf);

    const __half* Wl = g_W16 + (size_t)layer * 262144;
    const float*  bi = bih_all + layer * 1024;
    const float*  bh = bhh_all + layer * 1024;

    const int tid   = threadIdx.x;
    const int lane  = tid & 31;
    const int wid   = tid >> 5;
    const int warpM = wid >> 2;                     // 0..1
    const int warpN = wid & 3;                      // 0..3
    const int mBase = blockIdx.x * 128;
    const int nBase = blockIdx.y * 128;

    const int r0 = tid >> 3;                        // cp.async row (0..31)
    const int c0 = tid & 7;                         // 16B chunk (0..7)

    const int grp  = lane >> 3;
    const int rinl = lane & 7;
    const int aRow = warpM * 64 + (grp & 1) * 8 + rinl;
    const int aCol = (grp >> 1) * 8;
    const int bRowBase = warpN * 32 + rinl;
    const int bCol = ((lane >> 3) & 1) * 8;

    float acc[4][4][4];
#pragma unroll
    for (int i = 0; i < 4; ++i)
#pragma unroll
        for (int j = 0; j < 4; ++j)
#pragma unroll
            for (int v = 0; v < 4; ++v) acc[i][j][v] = 0.f;

    // ---- prologue: stage 0 into buffer 0
#pragma unroll
    for (int i = 0; i < 4; ++i) {
        int r = r0 + i * 32;
        int arow = mBase + r;
        if (arow > total - 1) arow = total - 1;
        cp16(sbase + (uint32_t)(r * AK + c0 * 8) * 2,
             Ah + (size_t)arow * 256 + c0 * 8);
        cp16(sbase + (uint32_t)(128 * AK + r * AK + c0 * 8) * 2,
             Wl + (size_t)(nBase + r) * 256 + c0 * 8);
    }
    asm volatile("cp.async.commit_group;" ::: "memory");

    for (int s = 0; s < 4; ++s) {
        if (s < 3) {
            const int ks  = s + 1;
            const int nbf = ks & 1;
#pragma unroll
            for (int i = 0; i < 4; ++i) {
                int r = r0 + i * 32;
                int arow = mBase + r;
                if (arow > total - 1) arow = total - 1;
                cp16(sbase + (uint32_t)(nbf * STAGE + r * AK + c0 * 8) * 2,
                     Ah + (size_t)arow * 256 + ks * 64 + c0 * 8);
                cp16(sbase + (uint32_t)(nbf * STAGE + 128 * AK + r * AK + c0 * 8) * 2,
                     Wl + (size_t)(nBase + r) * 256 + ks * 64 + c0 * 8);
            }
        }
        asm volatile("cp.async.commit_group;" ::: "memory");
        if (s < 3) asm volatile("cp.async.wait_group 1;" ::: "memory");
        else       asm volatile("cp.async.wait_group 0;" ::: "memory");
        __syncthreads();

        const int buf = s & 1;
        const uint32_t aTile = sbase + (uint32_t)(buf * STAGE) * 2;
        const uint32_t bTile = sbase + (uint32_t)(buf * STAGE + 128 * AK) * 2;

#pragma unroll
        for (int kk = 0; kk < 4; ++kk) {
            uint32_t af[4][4];
            uint32_t bf[4][2];
#pragma unroll
            for (int mf = 0; mf < 4; ++mf) {
                uint32_t aaddr = aTile +
                    (uint32_t)((aRow + mf * 16) * AK + kk * 16 + aCol) * 2;
                ldsm_x4(af[mf][0], af[mf][1], af[mf][2], af[mf][3], aaddr);
            }
#pragma unroll
            for (int nf = 0; nf < 4; ++nf) {
                uint32_t baddr = bTile +
                    (uint32_t)((bRowBase + nf * 8) * AK + kk * 16 + bCol) * 2;
                ldsm_x2(bf[nf][0], bf[nf][1], baddr);
            }
#pragma unroll
            for (int mf = 0; mf < 4; ++mf)
#pragma unroll
                for (int nf = 0; nf < 4; ++nf)
                    mma16816(acc[mf][nf],
                             af[mf][0], af[mf][1], af[mf][2], af[mf][3],
                             bf[nf][0], bf[nf][1]);
        }
        __syncthreads();
    }

    // ---- epilogue: bias add + scatter to g_gpre[dir][tok][g]
    const int mW = mBase + warpM * 64 + (lane >> 2);
    const int nW = nBase + warpN * 32 + ((lane & 3) << 1);
#pragma unroll
    for (int nf = 0; nf < 4; ++nf) {
        int n = nW + nf * 8;
        float bias0 = bi[n] + bh[n];
        float bias1 = bi[n + 1] + bh[n + 1];
        int dirr = n >> 9;
        int g    = n & 511;
        float* gp = g_gpre + (size_t)dirr * (size_t)total * 512 + g;
#pragma unroll
        for (int mf = 0; mf < 4; ++mf) {
            int m0 = mW + mf * 16;
            if (m0 < total) {
                float2 v = make_float2(acc[mf][nf][0] + bias0, acc[mf][nf][1] + bias1);
                *reinterpret_cast<float2*>(gp + (size_t)m0 * 512) = v;
            }
            int m1 = m0 + 8;
            if (m1 < total) {
                float2 v = make_float2(acc[mf][nf][2] + bias0, acc[mf][nf][3] + bias1);
                *reinterpret_cast<float2*>(gp + (size_t)m1 * 512) = v;
            }
        }
    }
}

// ------------------------------------------------------------- recurrence ---
// HW tanh: single MUFU op (sm_75+).
__device__ __forceinline__ float tanha(float x)
{
    float y;
    asm("tanh.approx.f32 %0, %1;" : "=f"(y) : "f"(x));
    return y;
}
__device__ __forceinline__ float sigf(float x)
{
    return fmaf(tanha(0.5f * x), 0.5f, 0.5f);
}

// 128 CTAs: blockIdx.x = dir*64 + b. 256 threads, 2 gates/thread (tid, tid+256).
// W_hh fully register-resident: k<64 fp32 f32x2 pairs, k>=64 fp16 half2.
// Both gates' accumulators updated inside ONE pass over h (no h register
// arrays -> no spills / duplicate loads). z exchanged as packed float2.
__global__ __launch_bounds__(256, 1)
void rec_kernel(const float* __restrict__ Whh_all,
                const float* __restrict__ h0,
                const float* __restrict__ c0,
                float* __restrict__ dout,
                int total, int T, int layer)
{
    __shared__ __align__(16) float  hs[128];
    __shared__ __align__(16) __half hsh[64];
    __shared__ __align__(16) float  zs[512];   // zs[2*t]=(z0,z1) of thread t
    __shared__ int   offs[TMAX];

    const int tid = threadIdx.x;
    const int dir = blockIdx.x >> 6;
    const int b   = blockIdx.x & 63;
    const int kix = 2 * layer + dir;

    const float* gpd = g_gpre + (size_t)dir * (size_t)total * 512;
    const float* W   = Whh_all + (size_t)kix * 512 * 128;

    for (int i = tid; i < T; i += 256) offs[i] = g_offsets[i];

    // k < 64 -> fp32 f32x2 register pairs (2 gates x 32 pairs)
    ull wr[2][32];
#pragma unroll
    for (int e = 0; e < 2; ++e) {
        const float* wg = &W[(tid + 256 * e) * 128];
#pragma unroll
        for (int p = 0; p < 32; ++p) {
            float2 wv = *reinterpret_cast<const float2*>(&wg[2 * p]);
            wr[e][p] = packf2(wv.x, wv.y);
        }
    }
    // k >= 64 -> fp16 half2 registers (2 gates x 32 half2)
    unsigned int whr[2][32];
#pragma unroll
    for (int e = 0; e < 2; ++e) {
        const float* wg = &W[(tid + 256 * e) * 128 + 64];
#pragma unroll
        for (int c = 0; c < 8; ++c) {
            float4 w0 = *reinterpret_cast<const float4*>(&wg[c * 8]);
            float4 w1 = *reinterpret_cast<const float4*>(&wg[c * 8 + 4]);
            whr[e][c * 4 + 0] = h2u(__floats2half2_rn(w0.x, w0.y));
            whr[e][c * 4 + 1] = h2u(__floats2half2_rn(w0.z, w0.w));
            whr[e][c * 4 + 2] = h2u(__floats2half2_rn(w1.x, w1.y));
            whr[e][c * 4 + 3] = h2u(__floats2half2_rn(w1.z, w1.w));
        }
    }

    float creg = 0.f;
    if (tid < 128) {
        float hv = h0[(size_t)kix * 8192 + b * 128 + tid];
        hs[tid] = hv;
        if (tid >= 64) hsh[tid - 64] = __float2half_rn(hv);
        creg = c0[(size_t)kix * 8192 + b * 128 + tid];
    }
    __syncthreads();

    const int  len = g_len[b];
    const bool fwd = (dir == 0);

    int   tok = offs[fwd ? 0 : (len - 1)] + b;
    float gcur0 = gpd[(size_t)tok * 512 + tid];
    float gcur1 = gpd[(size_t)tok * 512 + tid + 256];

    const double2* h2p = reinterpret_cast<const double2*>(hs);
    const uint4*   hhp = reinterpret_cast<const uint4*>(hsh);
    const __half2  hzero = __floats2half2_rn(0.f, 0.f);

    for (int s = 0; s < len; ++s) {
        int   toknext = 0;
        float gnext0 = 0.f, gnext1 = 0.f;
        if (s + 1 < len) {
            int tn  = fwd ? (s + 1) : (len - 2 - s);
            toknext = offs[tn] + b;
            gnext0  = gpd[(size_t)toknext * 512 + tid];
            gnext1  = gpd[(size_t)toknext * 512 + tid + 256];
        }

        // fp32 part (k<64): both gates share each h load
        ull a00 = 0ull, a01 = 0ull, a10 = 0ull, a11 = 0ull;
#pragma unroll
        for (int q = 0; q < 16; ++q) {
            double2 h2 = h2p[q];
            ull hx = __double_as_longlong(h2.x);
            ull hy = __double_as_longlong(h2.y);
            a00 = ffma2(wr[0][2 * q],     hx, a00);
            a01 = ffma2(wr[0][2 * q + 1], hy, a01);
            a10 = ffma2(wr[1][2 * q],     hx, a10);
            a11 = ffma2(wr[1][2 * q + 1], hy, a11);
        }
        // fp16 part (k>=64): both gates share each h load
        __half2 hc00 = hzero, hc01 = hzero, hc10 = hzero, hc11 = hzero;
#pragma unroll
        for (int c = 0; c < 8; ++c) {
            uint4 hv = hhp[c];
            hc00 = __hfma2(uh2(whr[0][c * 4 + 0]), uh2(hv.x), hc00);
            hc01 = __hfma2(uh2(whr[0][c * 4 + 1]), uh2(hv.y), hc01);
            hc00 = __hfma2(uh2(whr[0][c * 4 + 2]), uh2(hv.z), hc00);
            hc01 = __hfma2(uh2(whr[0][c * 4 + 3]), uh2(hv.w), hc01);
            hc10 = __hfma2(uh2(whr[1][c * 4 + 0]), uh2(hv.x), hc10);
            hc11 = __hfma2(uh2(whr[1][c * 4 + 1]), uh2(hv.y), hc11);
            hc10 = __hfma2(uh2(whr[1][c * 4 + 2]), uh2(hv.z), hc10);
            hc11 = __hfma2(uh2(whr[1][c * 4 + 3]), uh2(hv.w), hc11);
        }

        // identical summation order to previous rounds (bit-for-bit z)
        float2 fa0 = unpackf2(a00);
        float2 fb0 = unpackf2(a01);
        float2 f00 = __half22float2(hc00);
        float2 f01 = __half22float2(hc01);
        float z0 = gcur0 + (fa0.x + fa0.y) + (fb0.x + fb0.y)
                 + (f00.x + f00.y) + (f01.x + f01.y);
        float2 fa1 = unpackf2(a10);
        float2 fb1 = unpackf2(a11);
        float2 f10 = __half22float2(hc10);
        float2 f11 = __half22float2(hc11);
        float z1 = gcur1 + (fa1.x + fa1.y) + (fb1.x + fb1.y)
                 + (f10.x + f10.y) + (f11.x + f11.y);

        *reinterpret_cast<float2*>(&zs[2 * tid]) = make_float2(z0, z1);
        __syncthreads();

        if (tid < 128) {
            // thread t wrote (z_t, z_{t+256}): zs2[c]=(zi,zg), zs2[c+128]=(zf,zo)
            float2 v0 = *reinterpret_cast<const float2*>(&zs[2 * tid]);
            float2 v1 = *reinterpret_cast<const float2*>(&zs[2 * (tid + 128)]);
            float ig = sigf(v0.x);
            float fg = sigf(v1.x);
            float gv = tanha(v0.y);
            float og = sigf(v1.y);
            creg = fg * creg + ig * gv;
            float hv = og * tanha(creg);
            hs[tid] = hv;
            if (tid >= 64) hsh[tid - 64] = __float2half_rn(hv);
            if (layer == 0)
                g_out1h[(size_t)tok * 256 + dir * 128 + tid] = __float2half_rn(hv);
            else
                dout[(size_t)tok * 256 + dir * 128 + tid] = hv;
        }
        __syncthreads();

        gcur0 = gnext0;
        gcur1 = gnext1;
        tok   = toknext;
    }

    if (tid < 128) {
        float* hn = dout + (size_t)total * 256 + (size_t)kix * 8192 + (size_t)b * 128;
        float* cn = hn + 4 * 64 * 128;
        hn[tid] = hs[tid];
        cn[tid] = creg;
    }
}

// ---------------------------------------------------------------- launch ----
extern "C" void kernel_launch(void* const* d_in, const int* in_sizes, int n_in,
                              void* d_out, int out_size)
{
    const float* input       = (const float*)d_in[0];
    const int*   batch_sizes = (const int*)  d_in[1];
    const float* h0          = (const float*)d_in[2];
    const float* c0          = (const float*)d_in[3];
    const float* W_ih        = (const float*)d_in[4];
    const float* W_hh        = (const float*)d_in[5];
    const float* b_ih        = (const float*)d_in[6];
    const float* b_hh        = (const float*)d_in[7];
    float* out = (float*)d_out;

    int T     = in_sizes[1];
    int total = in_sizes[0] / 256;
    if (total > TOTAL_MAX) total = TOTAL_MAX;
    if (T > TMAX) T = TMAX;

    const int GEMM_SMEM = 2 * (2 * 128 * AK) * 2;                // 73728 B
    cudaFuncSetAttribute(gemm_hmma, cudaFuncAttributeMaxDynamicSharedMemorySize, GEMM_SMEM);

    setup_kernel<<<1, 1024>>>(batch_sizes, T);

    // fp16 prepass (single launch)
    __half* dA16;   cudaGetSymbolAddress((void**)&dA16, g_A16);
    __half* dW16;   cudaGetSymbolAddress((void**)&dW16, g_W16);
    __half* dOut1h; cudaGetSymbolAddress((void**)&dOut1h, g_out1h);
    {
        int n4a = in_sizes[0] / 4;
        int n4w = in_sizes[4] / 4;
        int n4  = n4a + n4w;
        cvt_kernel<<<(n4 + 255) / 256, 256>>>(input, dA16, n4a, W_ih, dW16, n4w);
    }

    dim3 ggrid((total + 127) / 128, 8);
    // layer 0
    gemm_hmma<<<ggrid, 256, GEMM_SMEM>>>(dA16, b_ih, b_hh, total, 0);
    rec_kernel<<<128, 256>>>(W_hh, h0, c0, out, total, T, 0);
    // layer 1
    gemm_hmma<<<ggrid, 256, GEMM_SMEM>>>(dOut1h, b_ih, b_hh, total, 1);
    rec_kernel<<<128, 256>>>(W_hh, h0, c0, out, total, T, 1);
}